// round 15
// baseline (speedup 1.0000x reference)
#include <cuda_runtime.h>
#include <cuda_bf16.h>
#include <math.h>
#include <stdint.h>

#define BL 2048      // BATCH*SEQ
#define SEQ 1024
#define DM 768
#define DI 1536
#define DTR 48
#define NS 16
#define XDBL 80      // DTR + 2*NS
#define VOCAB 50304

// ---------------- fp32 scratch ------------------------------------------------
__device__ float g_X [BL * DM];        // residual stream
__device__ float g_XZ[BL * 2 * DI];    // in_proj output (x | z)
__device__ float g_Xs[BL * DI];        // conv+silu(x) fp32
__device__ float g_db[BL * XDBL];      // x_proj output (dt_in | B | C)
__device__ float g_dbp[4 * BL * XDBL]; // x_proj split-K partials
__device__ float g_dt[BL * DI];        // softplus(dt_proj)

// ---------------- split-bf16 scratch -------------------------------------------
__device__ __nv_bfloat16 g_xnH[BL * DM],  g_xnL[BL * DM];    // rmsnorm out
__device__ __nv_bfloat16 g_ygH[BL * DI],  g_ygL[BL * DI];    // gated scan out
__device__ __nv_bfloat16 g_inwH[2 * 2 * DI * DM], g_inwL[2 * 2 * DI * DM];
__device__ __nv_bfloat16 g_otwH[2 * DM * DI],     g_otwL[2 * DM * DI];
__device__ __nv_bfloat16 g_lmwH[VOCAB * DM],      g_lmwL[VOCAB * DM];

// ---------------- helpers ----------------------------------------------------
__device__ __forceinline__ float siluf(float v) {
    return v / (1.f + __expf(-v));
}
__device__ __forceinline__ float softplusf(float v) {
    return v > 20.f ? v : log1pf(__expf(v));
}
__device__ __forceinline__ void split1(float v, __nv_bfloat16& h, __nv_bfloat16& l) {
    h = __float2bfloat16(v);
    l = __float2bfloat16(v - __bfloat162float(h));
}

// ---------------- fp32 -> (hi,lo) bf16 convert --------------------------------
__global__ void split_kernel(const float* __restrict__ x,
                             __nv_bfloat16* __restrict__ h,
                             __nv_bfloat16* __restrict__ l, int n4) {
    int i = blockIdx.x * blockDim.x + threadIdx.x;
    if (i >= n4) return;
    float4 v = ((const float4*)x)[i];
    __nv_bfloat16 h0, h1, h2, h3, l0, l1, l2, l3;
    split1(v.x, h0, l0); split1(v.y, h1, l1);
    split1(v.z, h2, l2); split1(v.w, h3, l3);
    ((__nv_bfloat162*)h)[i * 2 + 0] = __nv_bfloat162(h0, h1);
    ((__nv_bfloat162*)h)[i * 2 + 1] = __nv_bfloat162(h2, h3);
    ((__nv_bfloat162*)l)[i * 2 + 0] = __nv_bfloat162(l0, l1);
    ((__nv_bfloat162*)l)[i * 2 + 1] = __nv_bfloat162(l2, l3);
}

// ---------------- embedding --------------------------------------------------
__global__ void embed_kernel(const int* __restrict__ tokens,
                             const float* __restrict__ wte,
                             float* __restrict__ X) {
    int t = blockIdx.x;
    int tok = tokens[t];
    const float4* src = (const float4*)(wte + (size_t)tok * DM);
    float4* dst = (float4*)(X + (size_t)t * DM);
    for (int i = threadIdx.x; i < DM / 4; i += blockDim.x) dst[i] = src[i];
}

// ---------------- rmsnorm -> split bf16 ---------------------------------------
__global__ void rmsnorm_split_kernel(const float* __restrict__ x,
                                     __nv_bfloat16* __restrict__ oh,
                                     __nv_bfloat16* __restrict__ ol) {
    int t = blockIdx.x;
    const float* xr = x + (size_t)t * DM;
    float s = 0.f;
    for (int i = threadIdx.x; i < DM; i += blockDim.x) {
        float v = xr[i];
        s += v * v;
    }
#pragma unroll
    for (int off = 16; off; off >>= 1) s += __shfl_xor_sync(0xffffffffu, s, off);
    __shared__ float red[8];
    if ((threadIdx.x & 31) == 0) red[threadIdx.x >> 5] = s;
    __syncthreads();
    if (threadIdx.x < 32) {
        float v = (threadIdx.x < 8) ? red[threadIdx.x] : 0.f;
#pragma unroll
        for (int off = 4; off; off >>= 1) v += __shfl_xor_sync(0xffffffffu, v, off);
        if (threadIdx.x == 0) red[0] = v;
    }
    __syncthreads();
    float scale = rsqrtf(red[0] * (1.f / DM) + 1e-6f);
    for (int i = threadIdx.x; i < DM; i += blockDim.x) {
        __nv_bfloat16 h, l;
        split1(xr[i] * scale, h, l);
        oh[(size_t)t * DM + i] = h;
        ol[(size_t)t * DM + i] = l;
    }
}

// =============================================================================
// split-bf16 tensor-core TN GEMM (mma.sync m16n8k16), templated M-tile:
//   C[M,N] = (Ah+Al)[M,K] * (Bh+Bl)[N,K]^T (+ optional fp32 addsrc)
//   ~ Ah*Bh + Ah*Bl + Al*Bh
// BM x 128 block tile (BM=128 or 64), BK=32, XOR-swizzled SMEM, 3-stage
// cp.async, 8 warps, 2 CTAs/SM.
// Grid: blockIdx.x = M (fast), blockIdx.y = N. M%BM==0, N%128==0, K%32==0.
// =============================================================================
#define BKH 32
#define B_STG 8192

__device__ __forceinline__ unsigned swz(int row, int c) {
    return (unsigned)(row * 64 + ((c ^ ((row >> 1) & 3)) << 4));
}

__device__ __forceinline__ void cp_async16(unsigned dst, const void* src) {
    asm volatile("cp.async.cg.shared.global [%0], [%1], 16;\n"
                 :: "r"(dst), "l"(src));
}
__device__ __forceinline__ void cp_commit() {
    asm volatile("cp.async.commit_group;\n");
}
__device__ __forceinline__ void cp_wait1() {
    asm volatile("cp.async.wait_group 1;\n");
}
__device__ __forceinline__ void ldsm_x4(unsigned r[4], unsigned addr) {
    asm volatile("ldmatrix.sync.aligned.m8n8.x4.shared.b16 {%0,%1,%2,%3}, [%4];"
                 : "=r"(r[0]), "=r"(r[1]), "=r"(r[2]), "=r"(r[3]) : "r"(addr));
}

__device__ __forceinline__ void mma_bf16(float c[4], const unsigned a[4], const unsigned b[2]) {
    asm volatile(
        "mma.sync.aligned.m16n8k16.row.col.f32.bf16.bf16.f32 "
        "{%0,%1,%2,%3}, {%4,%5,%6,%7}, {%8,%9}, {%0,%1,%2,%3};\n"
        : "+f"(c[0]), "+f"(c[1]), "+f"(c[2]), "+f"(c[3])
        : "r"(a[0]), "r"(a[1]), "r"(a[2]), "r"(a[3]), "r"(b[0]), "r"(b[1]));
}

template <int BM>
__global__ __launch_bounds__(256, 2) void mma_tn_bf16_t(
    const __nv_bfloat16* __restrict__ Ah, const __nv_bfloat16* __restrict__ Al,
    const __nv_bfloat16* __restrict__ Bh, const __nv_bfloat16* __restrict__ Bl,
    const float* __restrict__ addsrc, float* __restrict__ C,
    int M, int N, int K) {
    extern __shared__ __nv_bfloat16 sm[];

    constexpr int A_STG = BM * 64;          // bytes per A matrix per stage
    constexpr int NWM = BM / 32;            // M warp subdivisions (4 or 2)
    constexpr int NNT = 2 * NWM;            // n8-tiles per warp (8 or 4)
    constexpr unsigned AHo = 0;
    constexpr unsigned ALo = 3 * A_STG;
    constexpr unsigned BHo = 6 * A_STG;
    constexpr unsigned BLo = 6 * A_STG + 3 * B_STG;

    const int tid  = threadIdx.x;
    const int bm   = blockIdx.x * BM;
    const int bn   = blockIdx.y << 7;
    const int warp = tid >> 5, lane = tid & 31;
    const int wm   = warp % NWM;
    const int wn   = warp / NWM;            // 0..(8/NWM - 1)
    const int g    = lane >> 2, tq = lane & 3;

    const int a_row = (lane & 7) + 8 * ((lane >> 3) & 1);
    const int a_c   = (lane >> 4);
    const int b_row = (lane & 7) + 8 * (lane >> 4);
    const int b_c   = ((lane >> 3) & 1);

    const int lrow = tid >> 2;            // 0..63
    const int lch  = tid & 3;             // chunk 0..3

    const unsigned sb = (unsigned)__cvta_generic_to_shared(sm);

    float acc[2][NNT][4];
#pragma unroll
    for (int i = 0; i < 2; i++)
#pragma unroll
        for (int j = 0; j < NNT; j++)
#pragma unroll
            for (int q = 0; q < 4; q++) acc[i][j][q] = 0.f;

    const int KT = K / BKH;

    auto load_tile = [&](int s, int kt) {
        const int kb = kt * BKH + lch * 8;
        // A tiles: BM rows
#pragma unroll
        for (int r = 0; r < BM / 64; r++) {
            int row = lrow + 64 * r;
            unsigned doff = (unsigned)(s * A_STG) + swz(row, lch);
            size_t agoff = (size_t)(bm + row) * K + kb;
            cp_async16(sb + AHo + doff, Ah + agoff);
            cp_async16(sb + ALo + doff, Al + agoff);
        }
        // B tiles: 128 rows
#pragma unroll
        for (int r = 0; r < 2; r++) {
            int row = lrow + 64 * r;
            unsigned doff = (unsigned)(s * B_STG) + swz(row, lch);
            size_t bgoff = (size_t)(bn + row) * K + kb;
            cp_async16(sb + BHo + doff, Bh + bgoff);
            cp_async16(sb + BLo + doff, Bl + bgoff);
        }
    };

    load_tile(0, 0);
    cp_commit();
    if (KT > 1) load_tile(1, 1);
    cp_commit();

    for (int kt = 0; kt < KT; kt++) {
        cp_wait1();
        __syncthreads();
        if (kt + 2 < KT) load_tile((kt + 2) % 3, kt + 2);
        cp_commit();

        const unsigned sta = (unsigned)((kt % 3) * A_STG);
        const unsigned stb = (unsigned)((kt % 3) * B_STG);

#pragma unroll
        for (int ks = 0; ks < 2; ks++) {
            unsigned ah[2][4], al[2][4];
#pragma unroll
            for (int mt = 0; mt < 2; mt++) {
                int row = wm * 32 + mt * 16 + a_row;
                unsigned off = sta + swz(row, ks * 2 + a_c);
                ldsm_x4(ah[mt], sb + AHo + off);
                ldsm_x4(al[mt], sb + ALo + off);
            }
            unsigned bh[NNT][2], bl[NNT][2];
#pragma unroll
            for (int grp = 0; grp < NNT / 2; grp++) {
                int row = wn * (8 * NNT) + grp * 16 + b_row;
                unsigned off = stb + swz(row, ks * 2 + b_c);
                unsigned t[4];
                ldsm_x4(t, sb + BHo + off);
                bh[grp * 2][0] = t[0]; bh[grp * 2][1] = t[1];
                bh[grp * 2 + 1][0] = t[2]; bh[grp * 2 + 1][1] = t[3];
                ldsm_x4(t, sb + BLo + off);
                bl[grp * 2][0] = t[0]; bl[grp * 2][1] = t[1];
                bl[grp * 2 + 1][0] = t[2]; bl[grp * 2 + 1][1] = t[3];
            }
#pragma unroll
            for (int mt = 0; mt < 2; mt++)
#pragma unroll
                for (int nt = 0; nt < NNT; nt++)
                    mma_bf16(acc[mt][nt], ah[mt], bh[nt]);
#pragma unroll
            for (int mt = 0; mt < 2; mt++)
#pragma unroll
                for (int nt = 0; nt < NNT; nt++)
                    mma_bf16(acc[mt][nt], ah[mt], bl[nt]);
#pragma unroll
            for (int mt = 0; mt < 2; mt++)
#pragma unroll
                for (int nt = 0; nt < NNT; nt++)
                    mma_bf16(acc[mt][nt], al[mt], bh[nt]);
        }
    }

    // ---- epilogue ----
#pragma unroll
    for (int mt = 0; mt < 2; mt++) {
        int row0 = bm + wm * 32 + mt * 16 + g;
#pragma unroll
        for (int nt = 0; nt < NNT; nt++) {
            int col = bn + wn * (8 * NNT) + nt * 8 + tq * 2;
            size_t o0 = (size_t)row0 * N + col;
            size_t o1 = (size_t)(row0 + 8) * N + col;
            float2 v0 = make_float2(acc[mt][nt][0], acc[mt][nt][1]);
            float2 v1 = make_float2(acc[mt][nt][2], acc[mt][nt][3]);
            if (addsrc) {
                const float2 r0 = *(const float2*)(addsrc + o0);
                const float2 r1 = *(const float2*)(addsrc + o1);
                v0.x += r0.x; v0.y += r0.y;
                v1.x += r1.x; v1.y += r1.y;
            }
            *(float2*)(C + o0) = v0;
            *(float2*)(C + o1) = v1;
        }
    }
}

// =============================================================================
// x_proj split-K fp32: dbp[slice][2048,80] = Xs[:, slice*384:+384] * W^T slice
// Grid: (BL/64, 4). Then xreduce sums the 4 partials (fixed order).
// =============================================================================
#define XP_CK 64
#define XP_SX_STR 68
#define XP_SW_STR 85
#define XP_KSL (DI / 4)

__global__ __launch_bounds__(256) void xproj_kernel(
    const float* __restrict__ Xs, const float* __restrict__ W,
    float* __restrict__ dbp) {
    __shared__ float sX[XP_CK * XP_SX_STR];   // [k][token]
    __shared__ float sW[XP_CK * XP_SW_STR];   // [k][out]

    const int tid = threadIdx.x;
    const int tx = tid & 15;
    const int ty = tid >> 4;
    const int tok0 = blockIdx.x * 64;
    const int kb0 = blockIdx.y * XP_KSL;
    float* dbo = dbp + (size_t)blockIdx.y * BL * XDBL;

    float acc[4][5] = {};

    for (int kb = kb0; kb < kb0 + XP_KSL; kb += XP_CK) {
        {
            int row = tid >> 2;
            int f4  = tid & 3;
#pragma unroll
            for (int i = 0; i < 4; i++) {
                int k0 = (f4 + i * 4) * 4;
                float4 v = *(const float4*)(Xs + (size_t)(tok0 + row) * DI + kb + k0);
                sX[(k0 + 0) * XP_SX_STR + row] = v.x;
                sX[(k0 + 1) * XP_SX_STR + row] = v.y;
                sX[(k0 + 2) * XP_SX_STR + row] = v.z;
                sX[(k0 + 3) * XP_SX_STR + row] = v.w;
            }
        }
#pragma unroll
        for (int i = 0; i < 5; i++) {
            int idx = tid + i * 256;
            if (idx < 1280) {
                int row = idx >> 4;
                int k0 = (idx & 15) * 4;
                float4 v = *(const float4*)(W + (size_t)row * DI + kb + k0);
                sW[(k0 + 0) * XP_SW_STR + row] = v.x;
                sW[(k0 + 1) * XP_SW_STR + row] = v.y;
                sW[(k0 + 2) * XP_SW_STR + row] = v.z;
                sW[(k0 + 3) * XP_SW_STR + row] = v.w;
            }
        }
        __syncthreads();
#pragma unroll 4
        for (int k = 0; k < XP_CK; k++) {
            float4 xv = *(const float4*)&sX[k * XP_SX_STR + ty * 4];
            float xa[4] = {xv.x, xv.y, xv.z, xv.w};
            float wv[5];
#pragma unroll
            for (int j = 0; j < 5; j++) wv[j] = sW[k * XP_SW_STR + tx * 5 + j];
#pragma unroll
            for (int i = 0; i < 4; i++)
#pragma unroll
                for (int j = 0; j < 5; j++)
                    acc[i][j] = fmaf(xa[i], wv[j], acc[i][j]);
        }
        __syncthreads();
    }

#pragma unroll
    for (int i = 0; i < 4; i++)
#pragma unroll
        for (int j = 0; j < 5; j++)
            dbo[(size_t)(tok0 + ty * 4 + i) * XDBL + tx * 5 + j] = acc[i][j];
}

__global__ void xreduce_kernel(const float* __restrict__ p,
                               float* __restrict__ db) {
    int i = blockIdx.x * blockDim.x + threadIdx.x;
    if (i >= BL * XDBL) return;
    db[i] = (p[i] + p[i + BL * XDBL])
          + (p[i + 2 * BL * XDBL] + p[i + 3 * BL * XDBL]);
}

// ---------------- depthwise causal conv (width 4) + silu ----------------------
__global__ void conv_silu_kernel(const float* __restrict__ XZ,
                                 const float* __restrict__ cw,
                                 const float* __restrict__ cb,
                                 float* __restrict__ out) {
    int idx = blockIdx.x * blockDim.x + threadIdx.x;
    if (idx >= BL * DI) return;
    int t = idx / DI, d = idx - t * DI;
    int l = t & (SEQ - 1);
    const float* w = cw + d * 4;
    float s = cb[d];
    s = fmaf(w[3], XZ[(size_t)t * (2 * DI) + d], s);
    if (l >= 1) s = fmaf(w[2], XZ[(size_t)(t - 1) * (2 * DI) + d], s);
    if (l >= 2) s = fmaf(w[1], XZ[(size_t)(t - 2) * (2 * DI) + d], s);
    if (l >= 3) s = fmaf(w[0], XZ[(size_t)(t - 3) * (2 * DI) + d], s);
    out[idx] = siluf(s);
}

// ---------------- dt_proj (K=48) + bias + softplus ----------------------------
__global__ void dtproj_kernel(const float* __restrict__ dbl,
                              const float* __restrict__ W,
                              const float* __restrict__ bias,
                              float* __restrict__ out) {
    int idx = blockIdx.x * blockDim.x + threadIdx.x;
    if (idx >= BL * DI) return;
    int t = idx / DI, d = idx - t * DI;
    const float4* a = (const float4*)(dbl + (size_t)t * XDBL);
    const float4* w = (const float4*)(W + (size_t)d * DTR);
    float s = bias[d];
#pragma unroll
    for (int r = 0; r < DTR / 4; r++) {
        float4 av = a[r], wv = w[r];
        s = fmaf(av.x, wv.x, s);
        s = fmaf(av.y, wv.y, s);
        s = fmaf(av.z, wv.z, s);
        s = fmaf(av.w, wv.w, s);
    }
    out[idx] = softplusf(s);
}

// ---------------- selective scan (smem-staged) + fused gate/split --------------
// Block = 256 threads = 16 channel-groups of 16 lanes. B/C staged once per
// block (channel-independent); dt/xs/z staged per-channel with coalesced
// chunk loads. Inner loop touches only smem -> no exposed global latency.
#define SC_CH 16
#define SC_TC 64

__global__ __launch_bounds__(256) void scan_kernel(
    const float* __restrict__ dbl,
    const float* __restrict__ dt,
    const float* __restrict__ xs,
    const float* __restrict__ XZ,
    const float* __restrict__ A_log,
    const float* __restrict__ Dvec,
    __nv_bfloat16* __restrict__ ygH,
    __nv_bfloat16* __restrict__ ygL) {
    __shared__ float sBC[SC_TC][32];      // [t][0:16)=B, [16:32)=C
    __shared__ float sDT[SC_TC][SC_CH];
    __shared__ float sXS[SC_TC][SC_CH];
    __shared__ float sZ [SC_TC][SC_CH];

    const int tid  = threadIdx.x;
    const int grp  = tid >> 4;            // channel group within block
    const int lane = tid & 15;            // state index
    const int ch   = blockIdx.x * SC_CH + grp;
    const int b    = ch / DI, d = ch - b * DI;
    const int tbase = b * SEQ;
    const int d0   = (blockIdx.x * SC_CH) % DI;  // block's first d (same batch)

    const float A  = -expf(A_log[d * NS + lane]);
    const float Dd = Dvec[d];
    float h = 0.f;

    const int ltt = tid >> 5, lcc = tid & 31;   // B/C loader mapping
    const int mtt = tid >> 4, mdd = tid & 15;   // dt/xs/z loader mapping

    for (int c0 = 0; c0 < SEQ; c0 += SC_TC) {
        __syncthreads();
#pragma unroll
        for (int it = 0; it < SC_TC; it += 8) {
            int t = tbase + c0 + it + ltt;
            sBC[it + ltt][lcc] = dbl[(size_t)t * XDBL + DTR + lcc];
        }
#pragma unroll
        for (int it = 0; it < SC_TC; it += 16) {
            int t = tbase + c0 + it + mtt;
            size_t o = (size_t)t * DI + d0 + mdd;
            sDT[it + mtt][mdd] = dt[o];
            sXS[it + mtt][mdd] = xs[o];
            sZ [it + mtt][mdd] = XZ[(size_t)t * (2 * DI) + DI + d0 + mdd];
        }
        __syncthreads();
#pragma unroll 4
        for (int tl = 0; tl < SC_TC; tl++) {
            float dtv = sDT[tl][grp];
            float xv  = sXS[tl][grp];
            float Bv  = sBC[tl][lane];
            float Cv  = sBC[tl][16 + lane];
            h = fmaf(__expf(dtv * A), h, dtv * Bv * xv);
            float p = h * Cv;
            p += __shfl_xor_sync(0xffffffffu, p, 8, 16);
            p += __shfl_xor_sync(0xffffffffu, p, 4, 16);
            p += __shfl_xor_sync(0xffffffffu, p, 2, 16);
            p += __shfl_xor_sync(0xffffffffu, p, 1, 16);
            if (lane == 0) {
                float v = fmaf(Dd, xv, p) * siluf(sZ[tl][grp]);
                __nv_bfloat16 hh, ll;
                split1(v, hh, ll);
                size_t o = (size_t)(tbase + c0 + tl) * DI + d;
                ygH[o] = hh;
                ygL[o] = ll;
            }
        }
    }
}

// ---------------- launch -------------------------------------------------------
extern "C" void kernel_launch(void* const* d_in, const int* in_sizes, int n_in,
                              void* d_out, int out_size) {
    const int*   tokens = (const int*)  d_in[0];
    const float* wte    = (const float*)d_in[1];
    const float* in_w   = (const float*)d_in[2];
    const float* conv_w = (const float*)d_in[3];
    const float* conv_b = (const float*)d_in[4];
    const float* xp_w   = (const float*)d_in[5];
    const float* dtp_w  = (const float*)d_in[6];
    const float* dtp_b  = (const float*)d_in[7];
    const float* out_w  = (const float*)d_in[8];
    const float* A_log  = (const float*)d_in[9];
    const float* Dvec   = (const float*)d_in[10];
    const float* lm_w   = (const float*)d_in[11];
    float* out = (float*)d_out;
    (void)in_sizes; (void)n_in; (void)out_size;

    float *X, *XZ, *Xs, *db, *dbp, *dtb;
    cudaGetSymbolAddress((void**)&X,  g_X);
    cudaGetSymbolAddress((void**)&XZ, g_XZ);
    cudaGetSymbolAddress((void**)&Xs, g_Xs);
    cudaGetSymbolAddress((void**)&db, g_db);
    cudaGetSymbolAddress((void**)&dbp, g_dbp);
    cudaGetSymbolAddress((void**)&dtb, g_dt);

    __nv_bfloat16 *xnH, *xnL, *ygH, *ygL;
    __nv_bfloat16 *inwH, *inwL, *otwH, *otwL, *lmwH, *lmwL;
    cudaGetSymbolAddress((void**)&xnH, g_xnH);
    cudaGetSymbolAddress((void**)&xnL, g_xnL);
    cudaGetSymbolAddress((void**)&ygH, g_ygH);
    cudaGetSymbolAddress((void**)&ygL, g_ygL);
    cudaGetSymbolAddress((void**)&inwH, g_inwH);
    cudaGetSymbolAddress((void**)&inwL, g_inwL);
    cudaGetSymbolAddress((void**)&otwH, g_otwH);
    cudaGetSymbolAddress((void**)&otwL, g_otwL);
    cudaGetSymbolAddress((void**)&lmwH, g_lmwH);
    cudaGetSymbolAddress((void**)&lmwL, g_lmwL);

    static cudaStream_t s_side = nullptr;
    static cudaEvent_t ev_fork = nullptr, ev_join = nullptr;
    if (!s_side) {
        cudaStreamCreateWithFlags(&s_side, cudaStreamNonBlocking);
        cudaEventCreateWithFlags(&ev_fork, cudaEventDisableTiming);
        cudaEventCreateWithFlags(&ev_join, cudaEventDisableTiming);
    }

    cudaFuncSetAttribute(mma_tn_bf16_t<128>,
                         cudaFuncAttributeMaxDynamicSharedMemorySize, 98304);
    cudaFuncSetAttribute(mma_tn_bf16_t<64>,
                         cudaFuncAttributeMaxDynamicSharedMemorySize, 73728);

    auto split_launch = [&](const float* src, __nv_bfloat16* h, __nv_bfloat16* l,
                            int n, cudaStream_t st) {
        int n4 = n / 4;
        split_kernel<<<(n4 + 255) / 256, 256, 0, st>>>(src, h, l, n4);
    };

    const int EW_BLOCKS = (BL * DI + 255) / 256;

    // Launch order: embed(0), split_inw(1), rmsnorm(2), GEMM(3) — `ncu -s 5`
    // (2 harness launches precede ours) profiles the in_proj GEMM.
    embed_kernel<<<BL, 256>>>(tokens, wte, X);                       // 0
    split_launch(in_w, inwH, inwL, 2 * 2 * DI * DM, 0);              // 1
    rmsnorm_split_kernel<<<BL, 256>>>(X, xnH, xnL);                  // 2
    mma_tn_bf16_t<128><<<dim3(BL / 128, (2 * DI) / 128), 256, 98304>>>( // 3
        xnH, xnL, inwH, inwL, nullptr, XZ, BL, 2 * DI, DM);

    // fork: out_w + lm_w splits overlap the compute-bound GEMMs
    cudaEventRecord(ev_fork, 0);
    cudaStreamWaitEvent(s_side, ev_fork, 0);
    split_launch(out_w, otwH, otwL, 2 * DM * DI, s_side);
    split_launch(lm_w,  lmwH, lmwL, VOCAB * DM,  s_side);
    cudaEventRecord(ev_join, s_side);

    bool joined = false;
    for (int layer = 0; layer < 2; layer++) {
        size_t inw_off = (size_t)layer * 2 * DI * DM;
        size_t otw_off = (size_t)layer * DM * DI;
        const float* conv_w_l = conv_w + (size_t)layer * DI * 4;
        const float* conv_b_l = conv_b + (size_t)layer * DI;
        const float* xp_w_l   = xp_w   + (size_t)layer * XDBL * DI;
        const float* dtp_w_l  = dtp_w  + (size_t)layer * DI * DTR;
        const float* dtp_b_l  = dtp_b  + (size_t)layer * DI;
        const float* A_log_l  = A_log  + (size_t)layer * DI * NS;
        const float* D_l      = Dvec   + (size_t)layer * DI;

        if (layer > 0) {
            rmsnorm_split_kernel<<<BL, 256>>>(X, xnH, xnL);
            mma_tn_bf16_t<128><<<dim3(BL / 128, (2 * DI) / 128), 256, 98304>>>(
                xnH, xnL, inwH + inw_off, inwL + inw_off, nullptr, XZ,
                BL, 2 * DI, DM);
        }
        conv_silu_kernel<<<EW_BLOCKS, 256>>>(XZ, conv_w_l, conv_b_l, Xs);
        xproj_kernel<<<dim3(BL / 64, 4), 256>>>(Xs, xp_w_l, dbp);
        xreduce_kernel<<<(BL * XDBL + 255) / 256, 256>>>(dbp, db);
        dtproj_kernel<<<EW_BLOCKS, 256>>>(db, dtp_w_l, dtp_b_l, dtb);
        scan_kernel<<<(2 * DI) / SC_CH, 256>>>(db, dtb, Xs, XZ,
                                               A_log_l, D_l, ygH, ygL);
        if (!joined) {
            cudaStreamWaitEvent(0, ev_join, 0);
            joined = true;
        }
        mma_tn_bf16_t<64><<<dim3(BL / 64, DM / 128), 256, 73728>>>(
            ygH, ygL, otwH + otw_off, otwL + otw_off, X, X, BL, DM, DI);
    }

    rmsnorm_split_kernel<<<BL, 256>>>(X, xnH, xnL);
    mma_tn_bf16_t<128><<<dim3(BL / 128, VOCAB / 128), 256, 98304>>>(
        xnH, xnL, lmwH, lmwL, nullptr, out, BL, VOCAB, DM);
}

// round 16
// speedup vs baseline: 1.1570x; 1.1570x over previous
#include <cuda_runtime.h>
#include <cuda_bf16.h>
#include <math.h>
#include <stdint.h>

#define BL 2048      // BATCH*SEQ
#define SEQ 1024
#define DM 768
#define DI 1536
#define DTR 48
#define NS 16
#define XDBL 80      // DTR + 2*NS
#define VOCAB 50304

// ---------------- fp32 scratch ------------------------------------------------
__device__ float g_X [BL * DM];        // residual stream
__device__ float g_XZ[BL * 2 * DI];    // in_proj output (x | z)
__device__ float g_Xs[BL * DI];        // conv+silu(x) fp32
__device__ float g_db[BL * XDBL];      // x_proj output (dt_in | B | C)
__device__ float g_dbp[4 * BL * XDBL]; // x_proj split-K partials
__device__ float g_dt[BL * DI];        // softplus(dt_proj)
__device__ float g_Y [BL * DI];        // scan output
__device__ float g_otp[2 * BL * DM];   // out_proj split-K partials

// ---------------- split-bf16 scratch -------------------------------------------
__device__ __nv_bfloat16 g_xnH[BL * DM],  g_xnL[BL * DM];    // rmsnorm out
__device__ __nv_bfloat16 g_ygH[BL * DI],  g_ygL[BL * DI];    // gated scan out
__device__ __nv_bfloat16 g_inwH[2 * 2 * DI * DM], g_inwL[2 * 2 * DI * DM];
__device__ __nv_bfloat16 g_otwH[2 * DM * DI],     g_otwL[2 * DM * DI];
__device__ __nv_bfloat16 g_lmwH[VOCAB * DM],      g_lmwL[VOCAB * DM];

// ---------------- helpers ----------------------------------------------------
__device__ __forceinline__ float siluf(float v) {
    return v / (1.f + __expf(-v));
}
__device__ __forceinline__ float softplusf(float v) {
    return v > 20.f ? v : log1pf(__expf(v));
}
__device__ __forceinline__ void split1(float v, __nv_bfloat16& h, __nv_bfloat16& l) {
    h = __float2bfloat16(v);
    l = __float2bfloat16(v - __bfloat162float(h));
}

// ---------------- fp32 -> (hi,lo) bf16 convert --------------------------------
__global__ void split_kernel(const float* __restrict__ x,
                             __nv_bfloat16* __restrict__ h,
                             __nv_bfloat16* __restrict__ l, int n4) {
    int i = blockIdx.x * blockDim.x + threadIdx.x;
    if (i >= n4) return;
    float4 v = ((const float4*)x)[i];
    __nv_bfloat16 h0, h1, h2, h3, l0, l1, l2, l3;
    split1(v.x, h0, l0); split1(v.y, h1, l1);
    split1(v.z, h2, l2); split1(v.w, h3, l3);
    ((__nv_bfloat162*)h)[i * 2 + 0] = __nv_bfloat162(h0, h1);
    ((__nv_bfloat162*)h)[i * 2 + 1] = __nv_bfloat162(h2, h3);
    ((__nv_bfloat162*)l)[i * 2 + 0] = __nv_bfloat162(l0, l1);
    ((__nv_bfloat162*)l)[i * 2 + 1] = __nv_bfloat162(l2, l3);
}

// ---------------- embedding --------------------------------------------------
__global__ void embed_kernel(const int* __restrict__ tokens,
                             const float* __restrict__ wte,
                             float* __restrict__ X) {
    int t = blockIdx.x;
    int tok = tokens[t];
    const float4* src = (const float4*)(wte + (size_t)tok * DM);
    float4* dst = (float4*)(X + (size_t)t * DM);
    for (int i = threadIdx.x; i < DM / 4; i += blockDim.x) dst[i] = src[i];
}

// ---------------- rmsnorm -> split bf16 ---------------------------------------
__global__ void rmsnorm_split_kernel(const float* __restrict__ x,
                                     __nv_bfloat16* __restrict__ oh,
                                     __nv_bfloat16* __restrict__ ol) {
    int t = blockIdx.x;
    const float* xr = x + (size_t)t * DM;
    float s = 0.f;
    for (int i = threadIdx.x; i < DM; i += blockDim.x) {
        float v = xr[i];
        s += v * v;
    }
#pragma unroll
    for (int off = 16; off; off >>= 1) s += __shfl_xor_sync(0xffffffffu, s, off);
    __shared__ float red[8];
    if ((threadIdx.x & 31) == 0) red[threadIdx.x >> 5] = s;
    __syncthreads();
    if (threadIdx.x < 32) {
        float v = (threadIdx.x < 8) ? red[threadIdx.x] : 0.f;
#pragma unroll
        for (int off = 4; off; off >>= 1) v += __shfl_xor_sync(0xffffffffu, v, off);
        if (threadIdx.x == 0) red[0] = v;
    }
    __syncthreads();
    float scale = rsqrtf(red[0] * (1.f / DM) + 1e-6f);
    for (int i = threadIdx.x; i < DM; i += blockDim.x) {
        __nv_bfloat16 h, l;
        split1(xr[i] * scale, h, l);
        oh[(size_t)t * DM + i] = h;
        ol[(size_t)t * DM + i] = l;
    }
}

// =============================================================================
// split-bf16 tensor-core TN GEMM (mma.sync m16n8k16):
//   C[M,N] = (Ah+Al)[M,K] * (Bh+Bl)[N,K]^T (+ optional fp32 addsrc)
//   ~ Ah*Bh + Ah*Bl + Al*Bh
// BM x 128 block tile, BK=32, XOR-swizzled SMEM, 3-stage cp.async, 8 warps,
// 2 CTAs/SM. SLICES: split-K via blockIdx.z (row stride = K*SLICES,
// C offset by z*M*N). SLICES=1 codegen identical to the non-sliced kernel.
// Grid: (M/BM, N/128, SLICES). M%BM==0, N%128==0, K%32==0.
// =============================================================================
#define BKH 32
#define B_STG 8192

__device__ __forceinline__ unsigned swz(int row, int c) {
    return (unsigned)(row * 64 + ((c ^ ((row >> 1) & 3)) << 4));
}

__device__ __forceinline__ void cp_async16(unsigned dst, const void* src) {
    asm volatile("cp.async.cg.shared.global [%0], [%1], 16;\n"
                 :: "r"(dst), "l"(src));
}
__device__ __forceinline__ void cp_commit() {
    asm volatile("cp.async.commit_group;\n");
}
__device__ __forceinline__ void cp_wait1() {
    asm volatile("cp.async.wait_group 1;\n");
}
__device__ __forceinline__ void ldsm_x4(unsigned r[4], unsigned addr) {
    asm volatile("ldmatrix.sync.aligned.m8n8.x4.shared.b16 {%0,%1,%2,%3}, [%4];"
                 : "=r"(r[0]), "=r"(r[1]), "=r"(r[2]), "=r"(r[3]) : "r"(addr));
}

__device__ __forceinline__ void mma_bf16(float c[4], const unsigned a[4], const unsigned b[2]) {
    asm volatile(
        "mma.sync.aligned.m16n8k16.row.col.f32.bf16.bf16.f32 "
        "{%0,%1,%2,%3}, {%4,%5,%6,%7}, {%8,%9}, {%0,%1,%2,%3};\n"
        : "+f"(c[0]), "+f"(c[1]), "+f"(c[2]), "+f"(c[3])
        : "r"(a[0]), "r"(a[1]), "r"(a[2]), "r"(a[3]), "r"(b[0]), "r"(b[1]));
}

template <int BM, int SLICES>
__global__ __launch_bounds__(256, 2) void mma_tn_bf16_t(
    const __nv_bfloat16* __restrict__ Ah, const __nv_bfloat16* __restrict__ Al,
    const __nv_bfloat16* __restrict__ Bh, const __nv_bfloat16* __restrict__ Bl,
    const float* __restrict__ addsrc, float* __restrict__ C,
    int M, int N, int K) {
    extern __shared__ __nv_bfloat16 sm[];

    constexpr int A_STG = BM * 64;          // bytes per A matrix per stage
    constexpr int NWM = BM / 32;            // M warp subdivisions (4 or 2)
    constexpr int NNT = 2 * NWM;            // n8-tiles per warp (8 or 4)
    constexpr unsigned AHo = 0;
    constexpr unsigned ALo = 3 * A_STG;
    constexpr unsigned BHo = 6 * A_STG;
    constexpr unsigned BLo = 6 * A_STG + 3 * B_STG;

    if constexpr (SLICES > 1) {
        const int slice = blockIdx.z;
        Ah += (size_t)slice * K;
        Al += (size_t)slice * K;
        Bh += (size_t)slice * K;
        Bl += (size_t)slice * K;
        C  += (size_t)slice * (size_t)M * N;
    }

    const int tid  = threadIdx.x;
    const int bm   = blockIdx.x * BM;
    const int bn   = blockIdx.y << 7;
    const int warp = tid >> 5, lane = tid & 31;
    const int wm   = warp % NWM;
    const int wn   = warp / NWM;            // 0..(8/NWM - 1)
    const int g    = lane >> 2, tq = lane & 3;

    const int a_row = (lane & 7) + 8 * ((lane >> 3) & 1);
    const int a_c   = (lane >> 4);
    const int b_row = (lane & 7) + 8 * (lane >> 4);
    const int b_c   = ((lane >> 3) & 1);

    const int lrow = tid >> 2;            // 0..63
    const int lch  = tid & 3;             // chunk 0..3

    const unsigned sb = (unsigned)__cvta_generic_to_shared(sm);

    float acc[2][NNT][4];
#pragma unroll
    for (int i = 0; i < 2; i++)
#pragma unroll
        for (int j = 0; j < NNT; j++)
#pragma unroll
            for (int q = 0; q < 4; q++) acc[i][j][q] = 0.f;

    const int KT = K / BKH;

    auto load_tile = [&](int s, int kt) {
        const int kb = kt * BKH + lch * 8;
        // A tiles: BM rows (row stride = K*SLICES, compile-time multiplier)
#pragma unroll
        for (int r = 0; r < BM / 64; r++) {
            int row = lrow + 64 * r;
            unsigned doff = (unsigned)(s * A_STG) + swz(row, lch);
            size_t agoff = (size_t)(bm + row) * (K * SLICES) + kb;
            cp_async16(sb + AHo + doff, Ah + agoff);
            cp_async16(sb + ALo + doff, Al + agoff);
        }
        // B tiles: 128 rows
#pragma unroll
        for (int r = 0; r < 2; r++) {
            int row = lrow + 64 * r;
            unsigned doff = (unsigned)(s * B_STG) + swz(row, lch);
            size_t bgoff = (size_t)(bn + row) * (K * SLICES) + kb;
            cp_async16(sb + BHo + doff, Bh + bgoff);
            cp_async16(sb + BLo + doff, Bl + bgoff);
        }
    };

    load_tile(0, 0);
    cp_commit();
    if (KT > 1) load_tile(1, 1);
    cp_commit();

    for (int kt = 0; kt < KT; kt++) {
        cp_wait1();
        __syncthreads();
        if (kt + 2 < KT) load_tile((kt + 2) % 3, kt + 2);
        cp_commit();

        const unsigned sta = (unsigned)((kt % 3) * A_STG);
        const unsigned stb = (unsigned)((kt % 3) * B_STG);

#pragma unroll
        for (int ks = 0; ks < 2; ks++) {
            unsigned ah[2][4], al[2][4];
#pragma unroll
            for (int mt = 0; mt < 2; mt++) {
                int row = wm * 32 + mt * 16 + a_row;
                unsigned off = sta + swz(row, ks * 2 + a_c);
                ldsm_x4(ah[mt], sb + AHo + off);
                ldsm_x4(al[mt], sb + ALo + off);
            }
            unsigned bh[NNT][2], bl[NNT][2];
#pragma unroll
            for (int grp = 0; grp < NNT / 2; grp++) {
                int row = wn * (8 * NNT) + grp * 16 + b_row;
                unsigned off = stb + swz(row, ks * 2 + b_c);
                unsigned t[4];
                ldsm_x4(t, sb + BHo + off);
                bh[grp * 2][0] = t[0]; bh[grp * 2][1] = t[1];
                bh[grp * 2 + 1][0] = t[2]; bh[grp * 2 + 1][1] = t[3];
                ldsm_x4(t, sb + BLo + off);
                bl[grp * 2][0] = t[0]; bl[grp * 2][1] = t[1];
                bl[grp * 2 + 1][0] = t[2]; bl[grp * 2 + 1][1] = t[3];
            }
#pragma unroll
            for (int mt = 0; mt < 2; mt++)
#pragma unroll
                for (int nt = 0; nt < NNT; nt++)
                    mma_bf16(acc[mt][nt], ah[mt], bh[nt]);
#pragma unroll
            for (int mt = 0; mt < 2; mt++)
#pragma unroll
                for (int nt = 0; nt < NNT; nt++)
                    mma_bf16(acc[mt][nt], ah[mt], bl[nt]);
#pragma unroll
            for (int mt = 0; mt < 2; mt++)
#pragma unroll
                for (int nt = 0; nt < NNT; nt++)
                    mma_bf16(acc[mt][nt], al[mt], bh[nt]);
        }
    }

    // ---- epilogue ----
#pragma unroll
    for (int mt = 0; mt < 2; mt++) {
        int row0 = bm + wm * 32 + mt * 16 + g;
#pragma unroll
        for (int nt = 0; nt < NNT; nt++) {
            int col = bn + wn * (8 * NNT) + nt * 8 + tq * 2;
            size_t o0 = (size_t)row0 * N + col;
            size_t o1 = (size_t)(row0 + 8) * N + col;
            float2 v0 = make_float2(acc[mt][nt][0], acc[mt][nt][1]);
            float2 v1 = make_float2(acc[mt][nt][2], acc[mt][nt][3]);
            if (addsrc) {
                const float2 r0 = *(const float2*)(addsrc + o0);
                const float2 r1 = *(const float2*)(addsrc + o1);
                v0.x += r0.x; v0.y += r0.y;
                v1.x += r1.x; v1.y += r1.y;
            }
            *(float2*)(C + o0) = v0;
            *(float2*)(C + o1) = v1;
        }
    }
}

// ---------------- out_proj split-K reduce + residual add ----------------------
__global__ void resadd_kernel(const float* __restrict__ p,
                              float* __restrict__ X) {
    int i = blockIdx.x * blockDim.x + threadIdx.x;
    if (i >= BL * DM / 4) return;
    float4 x = ((const float4*)X)[i];
    float4 a = ((const float4*)p)[i];
    float4 b = ((const float4*)(p + BL * DM))[i];
    x.x += a.x + b.x; x.y += a.y + b.y;
    x.z += a.z + b.z; x.w += a.w + b.w;
    ((float4*)X)[i] = x;
}

// =============================================================================
// x_proj split-K fp32: dbp[slice][2048,80] = Xs[:, slice*384:+384] * W^T slice
// Grid: (BL/64, 4). Then xreduce sums the 4 partials (fixed order).
// =============================================================================
#define XP_CK 64
#define XP_SX_STR 68
#define XP_SW_STR 85
#define XP_KSL (DI / 4)

__global__ __launch_bounds__(256) void xproj_kernel(
    const float* __restrict__ Xs, const float* __restrict__ W,
    float* __restrict__ dbp) {
    __shared__ float sX[XP_CK * XP_SX_STR];   // [k][token]
    __shared__ float sW[XP_CK * XP_SW_STR];   // [k][out]

    const int tid = threadIdx.x;
    const int tx = tid & 15;
    const int ty = tid >> 4;
    const int tok0 = blockIdx.x * 64;
    const int kb0 = blockIdx.y * XP_KSL;
    float* dbo = dbp + (size_t)blockIdx.y * BL * XDBL;

    float acc[4][5] = {};

    for (int kb = kb0; kb < kb0 + XP_KSL; kb += XP_CK) {
        {
            int row = tid >> 2;
            int f4  = tid & 3;
#pragma unroll
            for (int i = 0; i < 4; i++) {
                int k0 = (f4 + i * 4) * 4;
                float4 v = *(const float4*)(Xs + (size_t)(tok0 + row) * DI + kb + k0);
                sX[(k0 + 0) * XP_SX_STR + row] = v.x;
                sX[(k0 + 1) * XP_SX_STR + row] = v.y;
                sX[(k0 + 2) * XP_SX_STR + row] = v.z;
                sX[(k0 + 3) * XP_SX_STR + row] = v.w;
            }
        }
#pragma unroll
        for (int i = 0; i < 5; i++) {
            int idx = tid + i * 256;
            if (idx < 1280) {
                int row = idx >> 4;
                int k0 = (idx & 15) * 4;
                float4 v = *(const float4*)(W + (size_t)row * DI + kb + k0);
                sW[(k0 + 0) * XP_SW_STR + row] = v.x;
                sW[(k0 + 1) * XP_SW_STR + row] = v.y;
                sW[(k0 + 2) * XP_SW_STR + row] = v.z;
                sW[(k0 + 3) * XP_SW_STR + row] = v.w;
            }
        }
        __syncthreads();
#pragma unroll 4
        for (int k = 0; k < XP_CK; k++) {
            float4 xv = *(const float4*)&sX[k * XP_SX_STR + ty * 4];
            float xa[4] = {xv.x, xv.y, xv.z, xv.w};
            float wv[5];
#pragma unroll
            for (int j = 0; j < 5; j++) wv[j] = sW[k * XP_SW_STR + tx * 5 + j];
#pragma unroll
            for (int i = 0; i < 4; i++)
#pragma unroll
                for (int j = 0; j < 5; j++)
                    acc[i][j] = fmaf(xa[i], wv[j], acc[i][j]);
        }
        __syncthreads();
    }

#pragma unroll
    for (int i = 0; i < 4; i++)
#pragma unroll
        for (int j = 0; j < 5; j++)
            dbo[(size_t)(tok0 + ty * 4 + i) * XDBL + tx * 5 + j] = acc[i][j];
}

__global__ void xreduce_kernel(const float* __restrict__ p,
                               float* __restrict__ db) {
    int i = blockIdx.x * blockDim.x + threadIdx.x;
    if (i >= BL * XDBL) return;
    db[i] = (p[i] + p[i + BL * XDBL])
          + (p[i + 2 * BL * XDBL] + p[i + 3 * BL * XDBL]);
}

// ---------------- depthwise causal conv (width 4) + silu ----------------------
__global__ void conv_silu_kernel(const float* __restrict__ XZ,
                                 const float* __restrict__ cw,
                                 const float* __restrict__ cb,
                                 float* __restrict__ out) {
    int idx = blockIdx.x * blockDim.x + threadIdx.x;
    if (idx >= BL * DI) return;
    int t = idx / DI, d = idx - t * DI;
    int l = t & (SEQ - 1);
    const float* w = cw + d * 4;
    float s = cb[d];
    s = fmaf(w[3], XZ[(size_t)t * (2 * DI) + d], s);
    if (l >= 1) s = fmaf(w[2], XZ[(size_t)(t - 1) * (2 * DI) + d], s);
    if (l >= 2) s = fmaf(w[1], XZ[(size_t)(t - 2) * (2 * DI) + d], s);
    if (l >= 3) s = fmaf(w[0], XZ[(size_t)(t - 3) * (2 * DI) + d], s);
    out[idx] = siluf(s);
}

// ---------------- dt_proj (K=48) + bias + softplus ----------------------------
__global__ void dtproj_kernel(const float* __restrict__ dbl,
                              const float* __restrict__ W,
                              const float* __restrict__ bias,
                              float* __restrict__ out) {
    int idx = blockIdx.x * blockDim.x + threadIdx.x;
    if (idx >= BL * DI) return;
    int t = idx / DI, d = idx - t * DI;
    const float4* a = (const float4*)(dbl + (size_t)t * XDBL);
    const float4* w = (const float4*)(W + (size_t)d * DTR);
    float s = bias[d];
#pragma unroll
    for (int r = 0; r < DTR / 4; r++) {
        float4 av = a[r], wv = w[r];
        s = fmaf(av.x, wv.x, s);
        s = fmaf(av.y, wv.y, s);
        s = fmaf(av.z, wv.z, s);
        s = fmaf(av.w, wv.w, s);
    }
    out[idx] = softplusf(s);
}

// ---------------- selective scan (smem-staged chunks) --------------------------
#define SC_CH 16
#define SC_TC 64

__global__ __launch_bounds__(256) void scan_kernel(
    const float* __restrict__ dbl,
    const float* __restrict__ dt,
    const float* __restrict__ xs,
    const float* __restrict__ A_log,
    const float* __restrict__ Dvec,
    float* __restrict__ y) {
    __shared__ float sBC[SC_TC][32];      // [t][0:16)=B, [16:32)=C
    __shared__ float sDT[SC_TC][SC_CH];
    __shared__ float sXS[SC_TC][SC_CH];

    const int tid  = threadIdx.x;
    const int grp  = tid >> 4;            // channel group within block
    const int lane = tid & 15;            // state index
    const int ch   = blockIdx.x * SC_CH + grp;
    const int b    = ch / DI, d = ch - b * DI;
    const int tbase = b * SEQ;
    const int d0   = (blockIdx.x * SC_CH) % DI;  // block's first d (same batch)

    const float A  = -expf(A_log[d * NS + lane]);
    const float Dd = Dvec[d];
    float h = 0.f;

    const int ltt = tid >> 5, lcc = tid & 31;   // B/C loader mapping
    const int mtt = tid >> 4, mdd = tid & 15;   // dt/xs loader mapping

    for (int c0 = 0; c0 < SEQ; c0 += SC_TC) {
        __syncthreads();
#pragma unroll
        for (int it = 0; it < SC_TC; it += 8) {
            int t = tbase + c0 + it + ltt;
            sBC[it + ltt][lcc] = dbl[(size_t)t * XDBL + DTR + lcc];
        }
#pragma unroll
        for (int it = 0; it < SC_TC; it += 16) {
            int t = tbase + c0 + it + mtt;
            size_t o = (size_t)t * DI + d0 + mdd;
            sDT[it + mtt][mdd] = dt[o];
            sXS[it + mtt][mdd] = xs[o];
        }
        __syncthreads();
#pragma unroll 4
        for (int tl = 0; tl < SC_TC; tl++) {
            float dtv = sDT[tl][grp];
            float xv  = sXS[tl][grp];
            float Bv  = sBC[tl][lane];
            float Cv  = sBC[tl][16 + lane];
            h = fmaf(__expf(dtv * A), h, dtv * Bv * xv);
            float p = h * Cv;
            p += __shfl_xor_sync(0xffffffffu, p, 8, 16);
            p += __shfl_xor_sync(0xffffffffu, p, 4, 16);
            p += __shfl_xor_sync(0xffffffffu, p, 2, 16);
            p += __shfl_xor_sync(0xffffffffu, p, 1, 16);
            if (lane == 0)
                y[(size_t)(tbase + c0 + tl) * DI + d] = fmaf(Dd, xv, p);
        }
    }
}

// ---------------- gate: yg = y * silu(z), split out ----------------------------
__global__ void gate_split_kernel(const float* __restrict__ XZ,
                                  const float* __restrict__ Y,
                                  __nv_bfloat16* __restrict__ oh,
                                  __nv_bfloat16* __restrict__ ol) {
    int idx = blockIdx.x * blockDim.x + threadIdx.x;
    if (idx >= BL * DI) return;
    int t = idx / DI, d = idx - t * DI;
    float z = XZ[(size_t)t * (2 * DI) + DI + d];
    float v = Y[idx] * siluf(z);
    __nv_bfloat16 h, lo;
    split1(v, h, lo);
    oh[idx] = h;
    ol[idx] = lo;
}

// ---------------- launch -------------------------------------------------------
extern "C" void kernel_launch(void* const* d_in, const int* in_sizes, int n_in,
                              void* d_out, int out_size) {
    const int*   tokens = (const int*)  d_in[0];
    const float* wte    = (const float*)d_in[1];
    const float* in_w   = (const float*)d_in[2];
    const float* conv_w = (const float*)d_in[3];
    const float* conv_b = (const float*)d_in[4];
    const float* xp_w   = (const float*)d_in[5];
    const float* dtp_w  = (const float*)d_in[6];
    const float* dtp_b  = (const float*)d_in[7];
    const float* out_w  = (const float*)d_in[8];
    const float* A_log  = (const float*)d_in[9];
    const float* Dvec   = (const float*)d_in[10];
    const float* lm_w   = (const float*)d_in[11];
    float* out = (float*)d_out;
    (void)in_sizes; (void)n_in; (void)out_size;

    float *X, *XZ, *Xs, *db, *dbp, *dtb, *Y, *otp;
    cudaGetSymbolAddress((void**)&X,  g_X);
    cudaGetSymbolAddress((void**)&XZ, g_XZ);
    cudaGetSymbolAddress((void**)&Xs, g_Xs);
    cudaGetSymbolAddress((void**)&db, g_db);
    cudaGetSymbolAddress((void**)&dbp, g_dbp);
    cudaGetSymbolAddress((void**)&dtb, g_dt);
    cudaGetSymbolAddress((void**)&Y,  g_Y);
    cudaGetSymbolAddress((void**)&otp, g_otp);

    __nv_bfloat16 *xnH, *xnL, *ygH, *ygL;
    __nv_bfloat16 *inwH, *inwL, *otwH, *otwL, *lmwH, *lmwL;
    cudaGetSymbolAddress((void**)&xnH, g_xnH);
    cudaGetSymbolAddress((void**)&xnL, g_xnL);
    cudaGetSymbolAddress((void**)&ygH, g_ygH);
    cudaGetSymbolAddress((void**)&ygL, g_ygL);
    cudaGetSymbolAddress((void**)&inwH, g_inwH);
    cudaGetSymbolAddress((void**)&inwL, g_inwL);
    cudaGetSymbolAddress((void**)&otwH, g_otwH);
    cudaGetSymbolAddress((void**)&otwL, g_otwL);
    cudaGetSymbolAddress((void**)&lmwH, g_lmwH);
    cudaGetSymbolAddress((void**)&lmwL, g_lmwL);

    static cudaStream_t s_side = nullptr;
    static cudaEvent_t ev_fork = nullptr, ev_join = nullptr;
    if (!s_side) {
        cudaStreamCreateWithFlags(&s_side, cudaStreamNonBlocking);
        cudaEventCreateWithFlags(&ev_fork, cudaEventDisableTiming);
        cudaEventCreateWithFlags(&ev_join, cudaEventDisableTiming);
    }

    cudaFuncSetAttribute((const void*)mma_tn_bf16_t<128, 1>,
                         cudaFuncAttributeMaxDynamicSharedMemorySize, 98304);
    cudaFuncSetAttribute((const void*)mma_tn_bf16_t<64, 2>,
                         cudaFuncAttributeMaxDynamicSharedMemorySize, 73728);

    auto split_launch = [&](const float* src, __nv_bfloat16* h, __nv_bfloat16* l,
                            int n, cudaStream_t st) {
        int n4 = n / 4;
        split_kernel<<<(n4 + 255) / 256, 256, 0, st>>>(src, h, l, n4);
    };

    const int EW_BLOCKS = (BL * DI + 255) / 256;

    // Launch order: embed(0), split_inw(1), rmsnorm(2), GEMM(3) — `ncu -s 5`
    // (2 harness launches precede ours) profiles the in_proj GEMM.
    embed_kernel<<<BL, 256>>>(tokens, wte, X);                       // 0
    split_launch(in_w, inwH, inwL, 2 * 2 * DI * DM, 0);              // 1
    rmsnorm_split_kernel<<<BL, 256>>>(X, xnH, xnL);                  // 2
    mma_tn_bf16_t<128, 1><<<dim3(BL / 128, (2 * DI) / 128), 256, 98304>>>( // 3
        xnH, xnL, inwH, inwL, nullptr, XZ, BL, 2 * DI, DM);

    // fork: out_w + lm_w splits overlap the compute-bound GEMMs
    cudaEventRecord(ev_fork, 0);
    cudaStreamWaitEvent(s_side, ev_fork, 0);
    split_launch(out_w, otwH, otwL, 2 * DM * DI, s_side);
    split_launch(lm_w,  lmwH, lmwL, VOCAB * DM,  s_side);
    cudaEventRecord(ev_join, s_side);

    bool joined = false;
    for (int layer = 0; layer < 2; layer++) {
        size_t inw_off = (size_t)layer * 2 * DI * DM;
        size_t otw_off = (size_t)layer * DM * DI;
        const float* conv_w_l = conv_w + (size_t)layer * DI * 4;
        const float* conv_b_l = conv_b + (size_t)layer * DI;
        const float* xp_w_l   = xp_w   + (size_t)layer * XDBL * DI;
        const float* dtp_w_l  = dtp_w  + (size_t)layer * DI * DTR;
        const float* dtp_b_l  = dtp_b  + (size_t)layer * DI;
        const float* A_log_l  = A_log  + (size_t)layer * DI * NS;
        const float* D_l      = Dvec   + (size_t)layer * DI;

        if (layer > 0) {
            rmsnorm_split_kernel<<<BL, 256>>>(X, xnH, xnL);
            mma_tn_bf16_t<128, 1><<<dim3(BL / 128, (2 * DI) / 128), 256, 98304>>>(
                xnH, xnL, inwH + inw_off, inwL + inw_off, nullptr, XZ,
                BL, 2 * DI, DM);
        }
        conv_silu_kernel<<<EW_BLOCKS, 256>>>(XZ, conv_w_l, conv_b_l, Xs);
        xproj_kernel<<<dim3(BL / 64, 4), 256>>>(Xs, xp_w_l, dbp);
        xreduce_kernel<<<(BL * XDBL + 255) / 256, 256>>>(dbp, db);
        dtproj_kernel<<<EW_BLOCKS, 256>>>(db, dtp_w_l, dtp_b_l, dtb);
        scan_kernel<<<(2 * DI) / SC_CH, 256>>>(db, dtb, Xs, A_log_l, D_l, Y);
        gate_split_kernel<<<EW_BLOCKS, 256>>>(XZ, Y, ygH, ygL);
        if (!joined) {
            cudaStreamWaitEvent(0, ev_join, 0);
            joined = true;
        }
        // out_proj split-K x2: partials to otp, then reduce + residual add
        mma_tn_bf16_t<64, 2><<<dim3(BL / 64, DM / 128, 2), 256, 73728>>>(
            ygH, ygL, otwH + otw_off, otwL + otw_off, nullptr, otp,
            BL, DM, DI / 2);
        resadd_kernel<<<(BL * DM / 4 + 255) / 256, 256>>>(otp, X);
    }

    rmsnorm_split_kernel<<<BL, 256>>>(X, xnH, xnL);
    mma_tn_bf16_t<128, 1><<<dim3(BL / 128, VOCAB / 128), 256, 98304>>>(
        xnH, xnL, lmwH, lmwL, nullptr, out, BL, VOCAB, DM);
}

// round 17
// speedup vs baseline: 1.2075x; 1.0436x over previous
#include <cuda_runtime.h>
#include <cuda_bf16.h>
#include <math.h>
#include <stdint.h>

#define BL 2048      // BATCH*SEQ
#define SEQ 1024
#define DM 768
#define DI 1536
#define DTR 48
#define NS 16
#define XDBL 80      // DTR + 2*NS
#define VOCAB 50304

// ---------------- fp32 scratch ------------------------------------------------
__device__ float g_X [BL * DM];        // residual stream
__device__ float g_XZ[BL * 2 * DI];    // in_proj output (x | z)
__device__ float g_Xs[BL * DI];        // conv+silu(x) fp32 (written by xproj_conv)
__device__ float g_db[BL * XDBL];      // x_proj output (dt_in | B | C)
__device__ float g_dbp[4 * BL * XDBL]; // x_proj split-K partials
__device__ float g_dt[BL * DI];        // softplus(dt_proj)
__device__ float g_Y [BL * DI];        // scan output
__device__ float g_otp[2 * BL * DM];   // out_proj split-K partials

// ---------------- split-bf16 scratch -------------------------------------------
__device__ __nv_bfloat16 g_xnH[BL * DM],  g_xnL[BL * DM];    // rmsnorm out
__device__ __nv_bfloat16 g_ygH[BL * DI],  g_ygL[BL * DI];    // gated scan out
__device__ __nv_bfloat16 g_inwH[2 * 2 * DI * DM], g_inwL[2 * 2 * DI * DM];
__device__ __nv_bfloat16 g_otwH[2 * DM * DI],     g_otwL[2 * DM * DI];
__device__ __nv_bfloat16 g_lmwH[VOCAB * DM],      g_lmwL[VOCAB * DM];

// ---------------- helpers ----------------------------------------------------
__device__ __forceinline__ float siluf(float v) {
    return v / (1.f + __expf(-v));
}
__device__ __forceinline__ float softplusf(float v) {
    return v > 20.f ? v : log1pf(__expf(v));
}
__device__ __forceinline__ void split1(float v, __nv_bfloat16& h, __nv_bfloat16& l) {
    h = __float2bfloat16(v);
    l = __float2bfloat16(v - __bfloat162float(h));
}

// ---------------- fp32 -> (hi,lo) bf16 convert --------------------------------
__global__ void split_kernel(const float* __restrict__ x,
                             __nv_bfloat16* __restrict__ h,
                             __nv_bfloat16* __restrict__ l, int n4) {
    int i = blockIdx.x * blockDim.x + threadIdx.x;
    if (i >= n4) return;
    float4 v = ((const float4*)x)[i];
    __nv_bfloat16 h0, h1, h2, h3, l0, l1, l2, l3;
    split1(v.x, h0, l0); split1(v.y, h1, l1);
    split1(v.z, h2, l2); split1(v.w, h3, l3);
    ((__nv_bfloat162*)h)[i * 2 + 0] = __nv_bfloat162(h0, h1);
    ((__nv_bfloat162*)h)[i * 2 + 1] = __nv_bfloat162(h2, h3);
    ((__nv_bfloat162*)l)[i * 2 + 0] = __nv_bfloat162(l0, l1);
    ((__nv_bfloat162*)l)[i * 2 + 1] = __nv_bfloat162(l2, l3);
}

// ---------------- embedding --------------------------------------------------
__global__ void embed_kernel(const int* __restrict__ tokens,
                             const float* __restrict__ wte,
                             float* __restrict__ X) {
    int t = blockIdx.x;
    int tok = tokens[t];
    const float4* src = (const float4*)(wte + (size_t)tok * DM);
    float4* dst = (float4*)(X + (size_t)t * DM);
    for (int i = threadIdx.x; i < DM / 4; i += blockDim.x) dst[i] = src[i];
}

// ---------------- rmsnorm -> split bf16 ---------------------------------------
__global__ void rmsnorm_split_kernel(const float* __restrict__ x,
                                     __nv_bfloat16* __restrict__ oh,
                                     __nv_bfloat16* __restrict__ ol) {
    int t = blockIdx.x;
    const float* xr = x + (size_t)t * DM;
    float s = 0.f;
    for (int i = threadIdx.x; i < DM; i += blockDim.x) {
        float v = xr[i];
        s += v * v;
    }
#pragma unroll
    for (int off = 16; off; off >>= 1) s += __shfl_xor_sync(0xffffffffu, s, off);
    __shared__ float red[8];
    if ((threadIdx.x & 31) == 0) red[threadIdx.x >> 5] = s;
    __syncthreads();
    if (threadIdx.x < 32) {
        float v = (threadIdx.x < 8) ? red[threadIdx.x] : 0.f;
#pragma unroll
        for (int off = 4; off; off >>= 1) v += __shfl_xor_sync(0xffffffffu, v, off);
        if (threadIdx.x == 0) red[0] = v;
    }
    __syncthreads();
    float scale = rsqrtf(red[0] * (1.f / DM) + 1e-6f);
    for (int i = threadIdx.x; i < DM; i += blockDim.x) {
        __nv_bfloat16 h, l;
        split1(xr[i] * scale, h, l);
        oh[(size_t)t * DM + i] = h;
        ol[(size_t)t * DM + i] = l;
    }
}

// =============================================================================
// split-bf16 tensor-core TN GEMM (mma.sync m16n8k16):
//   C[M,N] = (Ah+Al)[M,K] * (Bh+Bl)[N,K]^T (+ optional fp32 addsrc)
//   ~ Ah*Bh + Ah*Bl + Al*Bh
// BM x 128 block tile, BK=32, XOR-swizzled SMEM, 3-stage cp.async, 8 warps,
// 2 CTAs/SM. SLICES: split-K via blockIdx.z.
// =============================================================================
#define BKH 32
#define B_STG 8192

__device__ __forceinline__ unsigned swz(int row, int c) {
    return (unsigned)(row * 64 + ((c ^ ((row >> 1) & 3)) << 4));
}

__device__ __forceinline__ void cp_async16(unsigned dst, const void* src) {
    asm volatile("cp.async.cg.shared.global [%0], [%1], 16;\n"
                 :: "r"(dst), "l"(src));
}
__device__ __forceinline__ void cp_commit() {
    asm volatile("cp.async.commit_group;\n");
}
__device__ __forceinline__ void cp_wait1() {
    asm volatile("cp.async.wait_group 1;\n");
}
__device__ __forceinline__ void ldsm_x4(unsigned r[4], unsigned addr) {
    asm volatile("ldmatrix.sync.aligned.m8n8.x4.shared.b16 {%0,%1,%2,%3}, [%4];"
                 : "=r"(r[0]), "=r"(r[1]), "=r"(r[2]), "=r"(r[3]) : "r"(addr));
}

__device__ __forceinline__ void mma_bf16(float c[4], const unsigned a[4], const unsigned b[2]) {
    asm volatile(
        "mma.sync.aligned.m16n8k16.row.col.f32.bf16.bf16.f32 "
        "{%0,%1,%2,%3}, {%4,%5,%6,%7}, {%8,%9}, {%0,%1,%2,%3};\n"
        : "+f"(c[0]), "+f"(c[1]), "+f"(c[2]), "+f"(c[3])
        : "r"(a[0]), "r"(a[1]), "r"(a[2]), "r"(a[3]), "r"(b[0]), "r"(b[1]));
}

template <int BM, int SLICES>
__global__ __launch_bounds__(256, 2) void mma_tn_bf16_t(
    const __nv_bfloat16* __restrict__ Ah, const __nv_bfloat16* __restrict__ Al,
    const __nv_bfloat16* __restrict__ Bh, const __nv_bfloat16* __restrict__ Bl,
    const float* __restrict__ addsrc, float* __restrict__ C,
    int M, int N, int K) {
    extern __shared__ __nv_bfloat16 sm[];

    constexpr int A_STG = BM * 64;          // bytes per A matrix per stage
    constexpr int NWM = BM / 32;            // M warp subdivisions (4 or 2)
    constexpr int NNT = 2 * NWM;            // n8-tiles per warp (8 or 4)
    constexpr unsigned AHo = 0;
    constexpr unsigned ALo = 3 * A_STG;
    constexpr unsigned BHo = 6 * A_STG;
    constexpr unsigned BLo = 6 * A_STG + 3 * B_STG;

    if constexpr (SLICES > 1) {
        const int slice = blockIdx.z;
        Ah += (size_t)slice * K;
        Al += (size_t)slice * K;
        Bh += (size_t)slice * K;
        Bl += (size_t)slice * K;
        C  += (size_t)slice * (size_t)M * N;
    }

    const int tid  = threadIdx.x;
    const int bm   = blockIdx.x * BM;
    const int bn   = blockIdx.y << 7;
    const int warp = tid >> 5, lane = tid & 31;
    const int wm   = warp % NWM;
    const int wn   = warp / NWM;
    const int g    = lane >> 2, tq = lane & 3;

    const int a_row = (lane & 7) + 8 * ((lane >> 3) & 1);
    const int a_c   = (lane >> 4);
    const int b_row = (lane & 7) + 8 * (lane >> 4);
    const int b_c   = ((lane >> 3) & 1);

    const int lrow = tid >> 2;            // 0..63
    const int lch  = tid & 3;             // chunk 0..3

    const unsigned sb = (unsigned)__cvta_generic_to_shared(sm);

    float acc[2][NNT][4];
#pragma unroll
    for (int i = 0; i < 2; i++)
#pragma unroll
        for (int j = 0; j < NNT; j++)
#pragma unroll
            for (int q = 0; q < 4; q++) acc[i][j][q] = 0.f;

    const int KT = K / BKH;

    auto load_tile = [&](int s, int kt) {
        const int kb = kt * BKH + lch * 8;
#pragma unroll
        for (int r = 0; r < BM / 64; r++) {
            int row = lrow + 64 * r;
            unsigned doff = (unsigned)(s * A_STG) + swz(row, lch);
            size_t agoff = (size_t)(bm + row) * (K * SLICES) + kb;
            cp_async16(sb + AHo + doff, Ah + agoff);
            cp_async16(sb + ALo + doff, Al + agoff);
        }
#pragma unroll
        for (int r = 0; r < 2; r++) {
            int row = lrow + 64 * r;
            unsigned doff = (unsigned)(s * B_STG) + swz(row, lch);
            size_t bgoff = (size_t)(bn + row) * (K * SLICES) + kb;
            cp_async16(sb + BHo + doff, Bh + bgoff);
            cp_async16(sb + BLo + doff, Bl + bgoff);
        }
    };

    load_tile(0, 0);
    cp_commit();
    if (KT > 1) load_tile(1, 1);
    cp_commit();

    for (int kt = 0; kt < KT; kt++) {
        cp_wait1();
        __syncthreads();
        if (kt + 2 < KT) load_tile((kt + 2) % 3, kt + 2);
        cp_commit();

        const unsigned sta = (unsigned)((kt % 3) * A_STG);
        const unsigned stb = (unsigned)((kt % 3) * B_STG);

#pragma unroll
        for (int ks = 0; ks < 2; ks++) {
            unsigned ah[2][4], al[2][4];
#pragma unroll
            for (int mt = 0; mt < 2; mt++) {
                int row = wm * 32 + mt * 16 + a_row;
                unsigned off = sta + swz(row, ks * 2 + a_c);
                ldsm_x4(ah[mt], sb + AHo + off);
                ldsm_x4(al[mt], sb + ALo + off);
            }
            unsigned bh[NNT][2], bl[NNT][2];
#pragma unroll
            for (int grp = 0; grp < NNT / 2; grp++) {
                int row = wn * (8 * NNT) + grp * 16 + b_row;
                unsigned off = stb + swz(row, ks * 2 + b_c);
                unsigned t[4];
                ldsm_x4(t, sb + BHo + off);
                bh[grp * 2][0] = t[0]; bh[grp * 2][1] = t[1];
                bh[grp * 2 + 1][0] = t[2]; bh[grp * 2 + 1][1] = t[3];
                ldsm_x4(t, sb + BLo + off);
                bl[grp * 2][0] = t[0]; bl[grp * 2][1] = t[1];
                bl[grp * 2 + 1][0] = t[2]; bl[grp * 2 + 1][1] = t[3];
            }
#pragma unroll
            for (int mt = 0; mt < 2; mt++)
#pragma unroll
                for (int nt = 0; nt < NNT; nt++)
                    mma_bf16(acc[mt][nt], ah[mt], bh[nt]);
#pragma unroll
            for (int mt = 0; mt < 2; mt++)
#pragma unroll
                for (int nt = 0; nt < NNT; nt++)
                    mma_bf16(acc[mt][nt], ah[mt], bl[nt]);
#pragma unroll
            for (int mt = 0; mt < 2; mt++)
#pragma unroll
                for (int nt = 0; nt < NNT; nt++)
                    mma_bf16(acc[mt][nt], al[mt], bh[nt]);
        }
    }

    // ---- epilogue ----
#pragma unroll
    for (int mt = 0; mt < 2; mt++) {
        int row0 = bm + wm * 32 + mt * 16 + g;
#pragma unroll
        for (int nt = 0; nt < NNT; nt++) {
            int col = bn + wn * (8 * NNT) + nt * 8 + tq * 2;
            size_t o0 = (size_t)row0 * N + col;
            size_t o1 = (size_t)(row0 + 8) * N + col;
            float2 v0 = make_float2(acc[mt][nt][0], acc[mt][nt][1]);
            float2 v1 = make_float2(acc[mt][nt][2], acc[mt][nt][3]);
            if (addsrc) {
                const float2 r0 = *(const float2*)(addsrc + o0);
                const float2 r1 = *(const float2*)(addsrc + o1);
                v0.x += r0.x; v0.y += r0.y;
                v1.x += r1.x; v1.y += r1.y;
            }
            *(float2*)(C + o0) = v0;
            *(float2*)(C + o1) = v1;
        }
    }
}

// ---------------- out_proj split-K reduce + residual add ----------------------
__global__ void resadd_kernel(const float* __restrict__ p,
                              float* __restrict__ X) {
    int i = blockIdx.x * blockDim.x + threadIdx.x;
    if (i >= BL * DM / 4) return;
    float4 x = ((const float4*)X)[i];
    float4 a = ((const float4*)p)[i];
    float4 b = ((const float4*)(p + BL * DM))[i];
    x.x += a.x + b.x; x.y += a.y + b.y;
    x.z += a.z + b.z; x.w += a.w + b.w;
    ((float4*)X)[i] = x;
}

// =============================================================================
// x_proj + fused depthwise conv + silu (split-K over 4 K-slices):
//   Xs = silu(conv(XZ.x)) computed on the fly (bit-identical to the separate
//   conv kernel: zero-padded taps, same fma order), stored to g_Xs AND used
//   for dbp[slice] = Xs[:, slice-range] * W^T[slice-range].
// Grid: (BL/64, 4). Dynamic smem: sXZ[67][68] | sX[64*68] | sW[64*85].
// =============================================================================
#define XP_CK 64
#define XP_SX_STR 68
#define XP_SW_STR 85
#define XP_KSL (DI / 4)
#define XP_SXZ_F (67 * 68)
#define XP_SX_F  (XP_CK * XP_SX_STR)
#define XP_SW_F  (XP_CK * XP_SW_STR)
#define XP_SMEM  ((XP_SXZ_F + XP_SX_F + XP_SW_F) * 4)

__global__ __launch_bounds__(256) void xproj_conv_kernel(
    const float* __restrict__ XZ, const float* __restrict__ cw,
    const float* __restrict__ cb, const float* __restrict__ W,
    float* __restrict__ Xs, float* __restrict__ dbp) {
    extern __shared__ float smf[];
    float* sXZ = smf;                    // [67][68]
    float* sX  = smf + XP_SXZ_F;         // [k][token]
    float* sW  = smf + XP_SXZ_F + XP_SX_F;  // [k][out]

    const int tid = threadIdx.x;
    const int tx = tid & 15;
    const int ty = tid >> 4;
    const int tok0 = blockIdx.x * 64;
    const int kb0 = blockIdx.y * XP_KSL;
    const bool seqstart = (tok0 & (SEQ - 1)) == 0;
    float* dbo = dbp + (size_t)blockIdx.y * BL * XDBL;

    float acc[4][5] = {};

    for (int kb = kb0; kb < kb0 + XP_KSL; kb += XP_CK) {
        __syncthreads();   // previous iteration's readers done
        // stage XZ rows tok0-3 .. tok0+63, cols kb..kb+64 (x half of XZ)
        for (int j = tid; j < 67 * 16; j += 256) {
            int row = j >> 4, c4 = (j & 15) << 2;
            float4 v;
            if (row < 3 && seqstart) {
                v = make_float4(0.f, 0.f, 0.f, 0.f);
            } else {
                v = *(const float4*)(XZ + (size_t)(tok0 - 3 + row) * (2 * DI)
                                     + kb + c4);
            }
            *(float4*)&sXZ[row * 68 + c4] = v;
        }
        // stage W chunk transposed: 80 outs x 64 k = 1280 float4
#pragma unroll
        for (int i = 0; i < 5; i++) {
            int idx = tid + i * 256;
            if (idx < 1280) {
                int row = idx >> 4;
                int k0 = (idx & 15) * 4;
                float4 v = *(const float4*)(W + (size_t)row * DI + kb + k0);
                sW[(k0 + 0) * XP_SW_STR + row] = v.x;
                sW[(k0 + 1) * XP_SW_STR + row] = v.y;
                sW[(k0 + 2) * XP_SW_STR + row] = v.z;
                sW[(k0 + 3) * XP_SW_STR + row] = v.w;
            }
        }
        __syncthreads();
        // conv + silu -> sX[k][t] (transposed) and global Xs
        for (int o = tid; o < 4096; o += 256) {
            int t = o >> 6, d = o & 63;
            const float* w = cw + (kb + d) * 4;
            float s = cb[kb + d];
            s = fmaf(w[3], sXZ[(t + 3) * 68 + d], s);
            s = fmaf(w[2], sXZ[(t + 2) * 68 + d], s);
            s = fmaf(w[1], sXZ[(t + 1) * 68 + d], s);
            s = fmaf(w[0], sXZ[(t + 0) * 68 + d], s);
            float v = siluf(s);
            sX[d * XP_SX_STR + t] = v;
            Xs[(size_t)(tok0 + t) * DI + kb + d] = v;
        }
        __syncthreads();
#pragma unroll 4
        for (int k = 0; k < XP_CK; k++) {
            float4 xv = *(const float4*)&sX[k * XP_SX_STR + ty * 4];
            float xa[4] = {xv.x, xv.y, xv.z, xv.w};
            float wv[5];
#pragma unroll
            for (int j = 0; j < 5; j++) wv[j] = sW[k * XP_SW_STR + tx * 5 + j];
#pragma unroll
            for (int i = 0; i < 4; i++)
#pragma unroll
                for (int j = 0; j < 5; j++)
                    acc[i][j] = fmaf(xa[i], wv[j], acc[i][j]);
        }
    }

#pragma unroll
    for (int i = 0; i < 4; i++)
#pragma unroll
        for (int j = 0; j < 5; j++)
            dbo[(size_t)(tok0 + ty * 4 + i) * XDBL + tx * 5 + j] = acc[i][j];
}

__global__ void xreduce_kernel(const float* __restrict__ p,
                               float* __restrict__ db) {
    int i = blockIdx.x * blockDim.x + threadIdx.x;
    if (i >= BL * XDBL) return;
    db[i] = (p[i] + p[i + BL * XDBL])
          + (p[i + 2 * BL * XDBL] + p[i + 3 * BL * XDBL]);
}

// ---------------- dt_proj (K=48) + bias + softplus ----------------------------
__global__ void dtproj_kernel(const float* __restrict__ dbl,
                              const float* __restrict__ W,
                              const float* __restrict__ bias,
                              float* __restrict__ out) {
    int idx = blockIdx.x * blockDim.x + threadIdx.x;
    if (idx >= BL * DI) return;
    int t = idx / DI, d = idx - t * DI;
    const float4* a = (const float4*)(dbl + (size_t)t * XDBL);
    const float4* w = (const float4*)(W + (size_t)d * DTR);
    float s = bias[d];
#pragma unroll
    for (int r = 0; r < DTR / 4; r++) {
        float4 av = a[r], wv = w[r];
        s = fmaf(av.x, wv.x, s);
        s = fmaf(av.y, wv.y, s);
        s = fmaf(av.z, wv.z, s);
        s = fmaf(av.w, wv.w, s);
    }
    out[idx] = softplusf(s);
}

// ---------------- selective scan (smem-staged chunks) --------------------------
#define SC_CH 16
#define SC_TC 64

__global__ __launch_bounds__(256) void scan_kernel(
    const float* __restrict__ dbl,
    const float* __restrict__ dt,
    const float* __restrict__ xs,
    const float* __restrict__ A_log,
    const float* __restrict__ Dvec,
    float* __restrict__ y) {
    __shared__ float sBC[SC_TC][32];      // [t][0:16)=B, [16:32)=C
    __shared__ float sDT[SC_TC][SC_CH];
    __shared__ float sXS[SC_TC][SC_CH];

    const int tid  = threadIdx.x;
    const int grp  = tid >> 4;            // channel group within block
    const int lane = tid & 15;            // state index
    const int ch   = blockIdx.x * SC_CH + grp;
    const int b    = ch / DI, d = ch - b * DI;
    const int tbase = b * SEQ;
    const int d0   = (blockIdx.x * SC_CH) % DI;  // block's first d (same batch)

    const float A  = -expf(A_log[d * NS + lane]);
    const float Dd = Dvec[d];
    float h = 0.f;

    const int ltt = tid >> 5, lcc = tid & 31;   // B/C loader mapping
    const int mtt = tid >> 4, mdd = tid & 15;   // dt/xs loader mapping

    for (int c0 = 0; c0 < SEQ; c0 += SC_TC) {
        __syncthreads();
#pragma unroll
        for (int it = 0; it < SC_TC; it += 8) {
            int t = tbase + c0 + it + ltt;
            sBC[it + ltt][lcc] = dbl[(size_t)t * XDBL + DTR + lcc];
        }
#pragma unroll
        for (int it = 0; it < SC_TC; it += 16) {
            int t = tbase + c0 + it + mtt;
            size_t o = (size_t)t * DI + d0 + mdd;
            sDT[it + mtt][mdd] = dt[o];
            sXS[it + mtt][mdd] = xs[o];
        }
        __syncthreads();
#pragma unroll 4
        for (int tl = 0; tl < SC_TC; tl++) {
            float dtv = sDT[tl][grp];
            float xv  = sXS[tl][grp];
            float Bv  = sBC[tl][lane];
            float Cv  = sBC[tl][16 + lane];
            h = fmaf(__expf(dtv * A), h, dtv * Bv * xv);
            float p = h * Cv;
            p += __shfl_xor_sync(0xffffffffu, p, 8, 16);
            p += __shfl_xor_sync(0xffffffffu, p, 4, 16);
            p += __shfl_xor_sync(0xffffffffu, p, 2, 16);
            p += __shfl_xor_sync(0xffffffffu, p, 1, 16);
            if (lane == 0)
                y[(size_t)(tbase + c0 + tl) * DI + d] = fmaf(Dd, xv, p);
        }
    }
}

// ---------------- gate: yg = y * silu(z), split out ----------------------------
__global__ void gate_split_kernel(const float* __restrict__ XZ,
                                  const float* __restrict__ Y,
                                  __nv_bfloat16* __restrict__ oh,
                                  __nv_bfloat16* __restrict__ ol) {
    int idx = blockIdx.x * blockDim.x + threadIdx.x;
    if (idx >= BL * DI) return;
    int t = idx / DI, d = idx - t * DI;
    float z = XZ[(size_t)t * (2 * DI) + DI + d];
    float v = Y[idx] * siluf(z);
    __nv_bfloat16 h, lo;
    split1(v, h, lo);
    oh[idx] = h;
    ol[idx] = lo;
}

// ---------------- launch -------------------------------------------------------
extern "C" void kernel_launch(void* const* d_in, const int* in_sizes, int n_in,
                              void* d_out, int out_size) {
    const int*   tokens = (const int*)  d_in[0];
    const float* wte    = (const float*)d_in[1];
    const float* in_w   = (const float*)d_in[2];
    const float* conv_w = (const float*)d_in[3];
    const float* conv_b = (const float*)d_in[4];
    const float* xp_w   = (const float*)d_in[5];
    const float* dtp_w  = (const float*)d_in[6];
    const float* dtp_b  = (const float*)d_in[7];
    const float* out_w  = (const float*)d_in[8];
    const float* A_log  = (const float*)d_in[9];
    const float* Dvec   = (const float*)d_in[10];
    const float* lm_w   = (const float*)d_in[11];
    float* out = (float*)d_out;
    (void)in_sizes; (void)n_in; (void)out_size;

    float *X, *XZ, *Xs, *db, *dbp, *dtb, *Y, *otp;
    cudaGetSymbolAddress((void**)&X,  g_X);
    cudaGetSymbolAddress((void**)&XZ, g_XZ);
    cudaGetSymbolAddress((void**)&Xs, g_Xs);
    cudaGetSymbolAddress((void**)&db, g_db);
    cudaGetSymbolAddress((void**)&dbp, g_dbp);
    cudaGetSymbolAddress((void**)&dtb, g_dt);
    cudaGetSymbolAddress((void**)&Y,  g_Y);
    cudaGetSymbolAddress((void**)&otp, g_otp);

    __nv_bfloat16 *xnH, *xnL, *ygH, *ygL;
    __nv_bfloat16 *inwH, *inwL, *otwH, *otwL, *lmwH, *lmwL;
    cudaGetSymbolAddress((void**)&xnH, g_xnH);
    cudaGetSymbolAddress((void**)&xnL, g_xnL);
    cudaGetSymbolAddress((void**)&ygH, g_ygH);
    cudaGetSymbolAddress((void**)&ygL, g_ygL);
    cudaGetSymbolAddress((void**)&inwH, g_inwH);
    cudaGetSymbolAddress((void**)&inwL, g_inwL);
    cudaGetSymbolAddress((void**)&otwH, g_otwH);
    cudaGetSymbolAddress((void**)&otwL, g_otwL);
    cudaGetSymbolAddress((void**)&lmwH, g_lmwH);
    cudaGetSymbolAddress((void**)&lmwL, g_lmwL);

    static cudaStream_t s_side = nullptr;
    static cudaEvent_t ev_fork = nullptr, ev_join = nullptr;
    if (!s_side) {
        cudaStreamCreateWithFlags(&s_side, cudaStreamNonBlocking);
        cudaEventCreateWithFlags(&ev_fork, cudaEventDisableTiming);
        cudaEventCreateWithFlags(&ev_join, cudaEventDisableTiming);
    }

    cudaFuncSetAttribute((const void*)mma_tn_bf16_t<128, 1>,
                         cudaFuncAttributeMaxDynamicSharedMemorySize, 98304);
    cudaFuncSetAttribute((const void*)mma_tn_bf16_t<64, 2>,
                         cudaFuncAttributeMaxDynamicSharedMemorySize, 73728);
    cudaFuncSetAttribute((const void*)xproj_conv_kernel,
                         cudaFuncAttributeMaxDynamicSharedMemorySize, XP_SMEM);

    auto split_launch = [&](const float* src, __nv_bfloat16* h, __nv_bfloat16* l,
                            int n, cudaStream_t st) {
        int n4 = n / 4;
        split_kernel<<<(n4 + 255) / 256, 256, 0, st>>>(src, h, l, n4);
    };

    const int EW_BLOCKS = (BL * DI + 255) / 256;

    // Launch order: embed(0), split_inw(1), rmsnorm(2), GEMM(3) — `ncu -s 5`
    // (2 harness launches precede ours) profiles the in_proj GEMM.
    embed_kernel<<<BL, 256>>>(tokens, wte, X);                       // 0
    split_launch(in_w, inwH, inwL, 2 * 2 * DI * DM, 0);              // 1
    rmsnorm_split_kernel<<<BL, 256>>>(X, xnH, xnL);                  // 2
    mma_tn_bf16_t<128, 1><<<dim3(BL / 128, (2 * DI) / 128), 256, 98304>>>( // 3
        xnH, xnL, inwH, inwL, nullptr, XZ, BL, 2 * DI, DM);

    // fork: out_w + lm_w splits overlap the compute-bound GEMMs
    cudaEventRecord(ev_fork, 0);
    cudaStreamWaitEvent(s_side, ev_fork, 0);
    split_launch(out_w, otwH, otwL, 2 * DM * DI, s_side);
    split_launch(lm_w,  lmwH, lmwL, VOCAB * DM,  s_side);
    cudaEventRecord(ev_join, s_side);

    bool joined = false;
    for (int layer = 0; layer < 2; layer++) {
        size_t inw_off = (size_t)layer * 2 * DI * DM;
        size_t otw_off = (size_t)layer * DM * DI;
        const float* conv_w_l = conv_w + (size_t)layer * DI * 4;
        const float* conv_b_l = conv_b + (size_t)layer * DI;
        const float* xp_w_l   = xp_w   + (size_t)layer * XDBL * DI;
        const float* dtp_w_l  = dtp_w  + (size_t)layer * DI * DTR;
        const float* dtp_b_l  = dtp_b  + (size_t)layer * DI;
        const float* A_log_l  = A_log  + (size_t)layer * DI * NS;
        const float* D_l      = Dvec   + (size_t)layer * DI;

        if (layer > 0) {
            rmsnorm_split_kernel<<<BL, 256>>>(X, xnH, xnL);
            mma_tn_bf16_t<128, 1><<<dim3(BL / 128, (2 * DI) / 128), 256, 98304>>>(
                xnH, xnL, inwH + inw_off, inwL + inw_off, nullptr, XZ,
                BL, 2 * DI, DM);
        }
        // fused conv+silu + x_proj (writes Xs and dbp)
        xproj_conv_kernel<<<dim3(BL / 64, 4), 256, XP_SMEM>>>(
            XZ, conv_w_l, conv_b_l, xp_w_l, Xs, dbp);
        xreduce_kernel<<<(BL * XDBL + 255) / 256, 256>>>(dbp, db);
        dtproj_kernel<<<EW_BLOCKS, 256>>>(db, dtp_w_l, dtp_b_l, dtb);
        scan_kernel<<<(2 * DI) / SC_CH, 256>>>(db, dtb, Xs, A_log_l, D_l, Y);
        gate_split_kernel<<<EW_BLOCKS, 256>>>(XZ, Y, ygH, ygL);
        if (!joined) {
            cudaStreamWaitEvent(0, ev_join, 0);
            joined = true;
        }
        // out_proj split-K x2: partials to otp, then reduce + residual add
        mma_tn_bf16_t<64, 2><<<dim3(BL / 64, DM / 128, 2), 256, 73728>>>(
            ygH, ygL, otwH + otw_off, otwL + otw_off, nullptr, otp,
            BL, DM, DI / 2);
        resadd_kernel<<<(BL * DM / 4 + 255) / 256, 256>>>(otp, X);
    }

    rmsnorm_split_kernel<<<BL, 256>>>(X, xnH, xnL);
    mma_tn_bf16_t<128, 1><<<dim3(BL / 128, VOCAB / 128), 256, 98304>>>(
        xnH, xnL, lmwH, lmwL, nullptr, out, BL, VOCAB, DM);
}